// round 1
// baseline (speedup 1.0000x reference)
#include <cuda_runtime.h>

// Problem shape (fixed by the reference)
#define B_ 32
#define S_ 512
#define P_ 512
#define D_ 768
#define M_ (B_ * S_)   // 16384 token rows

// Scratch for precomputed norms (no cudaMalloc allowed)
__device__ float g_xsq[M_];
__device__ float g_psq[P_];

// ---------------------------------------------------------------------------
// Row-norm kernels: one warp per row, coalesced float4 reads + shfl reduce.
// ---------------------------------------------------------------------------
__global__ void xsq_kernel(const float* __restrict__ x) {
    int row  = blockIdx.x * (blockDim.x >> 5) + (threadIdx.x >> 5);
    int lane = threadIdx.x & 31;
    if (row >= M_) return;
    const float4* p = reinterpret_cast<const float4*>(x + (size_t)row * D_);
    float s = 0.f;
    #pragma unroll
    for (int i = lane; i < D_ / 4; i += 32) {   // 192 float4 / row -> 6 iters
        float4 v = p[i];
        s += v.x * v.x + v.y * v.y + v.z * v.z + v.w * v.w;
    }
    #pragma unroll
    for (int o = 16; o; o >>= 1) s += __shfl_xor_sync(0xffffffffu, s, o);
    if (lane == 0) g_xsq[row] = s;
}

__global__ void psq_kernel(const float* __restrict__ p) {
    int row  = blockIdx.x * (blockDim.x >> 5) + (threadIdx.x >> 5);
    int lane = threadIdx.x & 31;
    if (row >= P_) return;
    const float4* q = reinterpret_cast<const float4*>(p + (size_t)row * D_);
    float s = 0.f;
    #pragma unroll
    for (int i = lane; i < D_ / 4; i += 32) {
        float4 v = q[i];
        s += v.x * v.x + v.y * v.y + v.z * v.z + v.w * v.w;
    }
    #pragma unroll
    for (int o = 16; o; o >>= 1) s += __shfl_xor_sync(0xffffffffu, s, o);
    if (lane == 0) g_psq[row] = s;
}

// ---------------------------------------------------------------------------
// Fused distance GEMM:
//   C[m][n] = xsq[m] + psq[n] - 2 * sum_k A[m][k] * B[n][k]
// A: [M, D] row-major (inputs),  B: [P, D] row-major (prototypes)
// Tiling: BM=128, BN=128, BK=16, 256 threads, 8x8 per thread.
// ---------------------------------------------------------------------------
#define BM 128
#define BN 128
#define BK 16
#define TM 8
#define TN 8

__global__ __launch_bounds__(256)
void dist_gemm_kernel(const float* __restrict__ A,
                      const float* __restrict__ Bp,
                      float* __restrict__ C) {
    __shared__ float As[BK][BM];   // K-major -> M-major transpose in smem
    __shared__ float Bs[BK][BN];

    const int bx = blockIdx.x;            // N tile index (0..3)
    const int by = blockIdx.y;            // M tile index (0..127)
    const int tid = threadIdx.x;
    const int tx = tid & 15;              // 0..15 -> N sub-tile
    const int ty = tid >> 4;              // 0..15 -> M sub-tile

    const float* Ablk = A  + (size_t)by * BM * D_;
    const float* Bblk = Bp + (size_t)bx * BN * D_;

    // Global-load mapping: 128 rows x 4 float4 per tile, 256 threads -> 2 rows each
    const int lrow = tid >> 2;            // 0..63
    const int lcol = tid & 3;             // 0..3  (float4 column within BK=16)

    float acc[TM][TN] = {};

    for (int k0 = 0; k0 < D_; k0 += BK) {
        #pragma unroll
        for (int r = 0; r < 2; r++) {
            const int row = lrow + r * 64;
            float4 va = *reinterpret_cast<const float4*>(
                Ablk + (size_t)row * D_ + k0 + lcol * 4);
            As[lcol * 4 + 0][row] = va.x;
            As[lcol * 4 + 1][row] = va.y;
            As[lcol * 4 + 2][row] = va.z;
            As[lcol * 4 + 3][row] = va.w;
            float4 vb = *reinterpret_cast<const float4*>(
                Bblk + (size_t)row * D_ + k0 + lcol * 4);
            Bs[lcol * 4 + 0][row] = vb.x;
            Bs[lcol * 4 + 1][row] = vb.y;
            Bs[lcol * 4 + 2][row] = vb.z;
            Bs[lcol * 4 + 3][row] = vb.w;
        }
        __syncthreads();

        #pragma unroll
        for (int k = 0; k < BK; k++) {
            float a[TM], b[TN];
            #pragma unroll
            for (int i = 0; i < TM; i++) a[i] = As[k][ty * TM + i];
            #pragma unroll
            for (int j = 0; j < TN; j++) b[j] = Bs[k][tx * TN + j];
            #pragma unroll
            for (int i = 0; i < TM; i++)
                #pragma unroll
                for (int j = 0; j < TN; j++)
                    acc[i][j] = fmaf(a[i], b[j], acc[i][j]);
        }
        __syncthreads();
    }

    // Epilogue: distances = xsq + psq - 2*cross, vectorized float4 stores.
    const int gm0 = by * BM + ty * TM;
    const int gn0 = bx * BN + tx * TN;
    float ps[TN];
    #pragma unroll
    for (int j = 0; j < TN; j++) ps[j] = g_psq[gn0 + j];

    #pragma unroll
    for (int i = 0; i < TM; i++) {
        const float xs = g_xsq[gm0 + i];
        float* crow = C + (size_t)(gm0 + i) * P_ + gn0;
        #pragma unroll
        for (int j4 = 0; j4 < TN; j4 += 4) {
            float4 v;
            v.x = xs + ps[j4 + 0] - 2.f * acc[i][j4 + 0];
            v.y = xs + ps[j4 + 1] - 2.f * acc[i][j4 + 1];
            v.z = xs + ps[j4 + 2] - 2.f * acc[i][j4 + 2];
            v.w = xs + ps[j4 + 3] - 2.f * acc[i][j4 + 3];
            *reinterpret_cast<float4*>(crow + j4) = v;
        }
    }
}

// ---------------------------------------------------------------------------
// Launch: norms -> fused GEMM -> prototype passthrough copy (all default stream,
// graph-capturable, no allocations).
// ---------------------------------------------------------------------------
extern "C" void kernel_launch(void* const* d_in, const int* in_sizes, int n_in,
                              void* d_out, int out_size) {
    const float* inputs = (const float*)d_in[0];   // [B,S,D] = [M_, D_]
    const float* protos = (const float*)d_in[1];   // [P_, D_]
    float* out = (float*)d_out;

    // Row norms: 8 warps / block
    xsq_kernel<<<M_ / 8, 256>>>(inputs);
    psq_kernel<<<P_ / 8, 256>>>(protos);

    // Fused distance GEMM
    dim3 grid(P_ / BN, M_ / BM);   // (4, 128)
    dist_gemm_kernel<<<grid, 256>>>(inputs, protos, out);

    // Second output of the tuple: prototypes passed through unchanged.
    cudaMemcpyAsync(out + (size_t)M_ * P_, protos,
                    (size_t)P_ * D_ * sizeof(float),
                    cudaMemcpyDeviceToDevice);
}

// round 2
// speedup vs baseline: 3.2705x; 3.2705x over previous
#include <cuda_runtime.h>
#include <cstdint>

// Problem shape (fixed by the reference)
#define B_ 32
#define S_ 512
#define P_ 512
#define D_ 768
#define M_ (B_ * S_)   // 16384 token rows

// GEMM tiling
#define BM 128
#define BN 128
#define BK 16
#define KST 20                 // BK + 4 pad: bank = (4g+t)%32, conflict-free
#define NT (D_ / BK)           // 48 k-tiles

__device__ __forceinline__ unsigned smem_u32(const void* p) {
    return (unsigned)__cvta_generic_to_shared(p);
}

__device__ __forceinline__ void cp_async16(unsigned sdst, const void* gsrc) {
    asm volatile("cp.async.cg.shared.global [%0], [%1], 16;\n" ::"r"(sdst), "l"(gsrc));
}

// ---------------------------------------------------------------------------
// Fused: distances[m][n] = ||x_m||^2 + ||p_n||^2 - 2 <x_m, p_n>
// Cross term on TF32 tensor cores (mma.sync m16n8k8); row norms accumulated
// from the SAME smem-resident raw-f32 tiles (no extra global pass).
// A: [M_, D_] row-major, Bp: [P_, D_] row-major, C: [M_, P_].
// ---------------------------------------------------------------------------
__global__ __launch_bounds__(256, 2)
void dist_tf32_kernel(const float* __restrict__ A,
                      const float* __restrict__ Bp,
                      float* __restrict__ C) {
    __shared__ float As[2][BM][KST];
    __shared__ float Bs[2][BN][KST];
    __shared__ float sxs[BM];
    __shared__ float sps[BN];

    const int tid  = threadIdx.x;
    const int lane = tid & 31;
    const int warp = tid >> 5;
    const int wm   = warp & 3;       // 4 warps along M  -> warp tile M=32
    const int wn   = warp >> 2;      // 2 warps along N  -> warp tile N=64
    const int g    = lane >> 2;      // group id 0..7
    const int t    = lane & 3;       // thread-in-group 0..3

    const int bx = blockIdx.x;       // N tile (0..3)
    const int by = blockIdx.y;       // M tile (0..127)

    const float* Ablk = A  + (size_t)by * BM * D_;
    const float* Bblk = Bp + (size_t)bx * BN * D_;

    // cp.async mapping: 512 float4 per operand per stage, 2 each per thread.
    const int r0  = tid >> 2;                // 0..63
    const int kq0 = tid & 3;
    const int r1  = (tid + 256) >> 2;        // 64..127
    const int kq1 = (tid + 256) & 3;

    auto issue = [&](int s) {
        const int k0  = s * BK;
        const int buf = s & 1;
        cp_async16(smem_u32(&As[buf][r0][kq0 * 4]), Ablk + (size_t)r0 * D_ + k0 + kq0 * 4);
        cp_async16(smem_u32(&As[buf][r1][kq1 * 4]), Ablk + (size_t)r1 * D_ + k0 + kq1 * 4);
        cp_async16(smem_u32(&Bs[buf][r0][kq0 * 4]), Bblk + (size_t)r0 * D_ + k0 + kq0 * 4);
        cp_async16(smem_u32(&Bs[buf][r1][kq1 * 4]), Bblk + (size_t)r1 * D_ + k0 + kq1 * 4);
    };

    float c[2][8][4];
    #pragma unroll
    for (int i = 0; i < 2; i++)
        #pragma unroll
        for (int j = 0; j < 8; j++)
            #pragma unroll
            for (int q = 0; q < 4; q++) c[i][j][q] = 0.f;

    float xs[4] = {0.f, 0.f, 0.f, 0.f};    // row-norm partials (wn==0 warps)
    float ps[8] = {0.f, 0.f, 0.f, 0.f, 0.f, 0.f, 0.f, 0.f}; // proto norms (wm==0)

    issue(0);
    asm volatile("cp.async.commit_group;\n" ::: "memory");
    issue(1);
    asm volatile("cp.async.commit_group;\n" ::: "memory");

    for (int tt = 0; tt < NT; ++tt) {
        asm volatile("cp.async.wait_group 1;\n" ::: "memory");
        __syncthreads();
        const int buf = tt & 1;
        const float(*Asb)[KST] = As[buf];
        const float(*Bsb)[KST] = Bs[buf];

        #pragma unroll
        for (int kk = 0; kk < BK; kk += 8) {
            // ---- A fragments (m16 x k8, row-major) ----
            uint32_t af[2][4];
            #pragma unroll
            for (int i = 0; i < 2; i++) {
                const int m0 = wm * 32 + i * 16;
                const float a0 = Asb[m0 + g    ][kk + t];
                const float a1 = Asb[m0 + g + 8][kk + t];
                const float a2 = Asb[m0 + g    ][kk + t + 4];
                const float a3 = Asb[m0 + g + 8][kk + t + 4];
                af[i][0] = __float_as_uint(a0);
                af[i][1] = __float_as_uint(a1);
                af[i][2] = __float_as_uint(a2);
                af[i][3] = __float_as_uint(a3);
                if (wn == 0) {   // fuse ||x||^2 (raw f32, matches reference)
                    xs[i * 2 + 0] = fmaf(a0, a0, fmaf(a2, a2, xs[i * 2 + 0]));
                    xs[i * 2 + 1] = fmaf(a1, a1, fmaf(a3, a3, xs[i * 2 + 1]));
                }
            }
            // ---- B fragments (k8 x n8, col-major) + 16 mma ----
            #pragma unroll
            for (int j = 0; j < 8; j++) {
                const int n0 = wn * 64 + j * 8;
                const float b0 = Bsb[n0 + g][kk + t];
                const float b1 = Bsb[n0 + g][kk + t + 4];
                if (wm == 0) ps[j] = fmaf(b0, b0, fmaf(b1, b1, ps[j]));
                const uint32_t ub0 = __float_as_uint(b0);
                const uint32_t ub1 = __float_as_uint(b1);
                #pragma unroll
                for (int i = 0; i < 2; i++) {
                    asm volatile(
                        "mma.sync.aligned.m16n8k8.row.col.f32.tf32.tf32.f32 "
                        "{%0,%1,%2,%3}, {%4,%5,%6,%7}, {%8,%9}, {%0,%1,%2,%3};\n"
                        : "+f"(c[i][j][0]), "+f"(c[i][j][1]),
                          "+f"(c[i][j][2]), "+f"(c[i][j][3])
                        : "r"(af[i][0]), "r"(af[i][1]), "r"(af[i][2]), "r"(af[i][3]),
                          "r"(ub0), "r"(ub1));
                }
            }
        }
        __syncthreads();
        if (tt + 2 < NT) issue(tt + 2);
        asm volatile("cp.async.commit_group;\n" ::: "memory");
    }

    // ---- Norm reductions (over the 4 t-lanes) and smem exchange ----
    if (wn == 0) {
        #pragma unroll
        for (int q = 0; q < 4; q++) {
            xs[q] += __shfl_xor_sync(0xffffffffu, xs[q], 1);
            xs[q] += __shfl_xor_sync(0xffffffffu, xs[q], 2);
        }
        if (t == 0) {
            sxs[wm * 32 + g     ] = xs[0];
            sxs[wm * 32 + g + 8 ] = xs[1];
            sxs[wm * 32 + g + 16] = xs[2];
            sxs[wm * 32 + g + 24] = xs[3];
        }
    }
    if (wm == 0) {
        #pragma unroll
        for (int j = 0; j < 8; j++) {
            ps[j] += __shfl_xor_sync(0xffffffffu, ps[j], 1);
            ps[j] += __shfl_xor_sync(0xffffffffu, ps[j], 2);
            if (t == 0) sps[wn * 64 + j * 8 + g] = ps[j];
        }
    }
    __syncthreads();

    // ---- Epilogue: dist = xs + ps - 2*cross, float2 stores ----
    #pragma unroll
    for (int i = 0; i < 2; i++) {
        const int ml  = wm * 32 + i * 16 + g;
        const float x0 = sxs[ml];
        const float x1 = sxs[ml + 8];
        const int mg  = by * BM + ml;
        float* row0 = C + (size_t)mg * P_;
        float* row1 = C + (size_t)(mg + 8) * P_;
        #pragma unroll
        for (int j = 0; j < 8; j++) {
            const int nl = wn * 64 + j * 8 + 2 * t;
            const float p0 = sps[nl];
            const float p1 = sps[nl + 1];
            const int ng = bx * BN + nl;
            float2 v0, v1;
            v0.x = x0 + p0 - 2.f * c[i][j][0];
            v0.y = x0 + p1 - 2.f * c[i][j][1];
            v1.x = x1 + p0 - 2.f * c[i][j][2];
            v1.y = x1 + p1 - 2.f * c[i][j][3];
            *reinterpret_cast<float2*>(row0 + ng) = v0;
            *reinterpret_cast<float2*>(row1 + ng) = v1;
        }
    }
}

// ---------------------------------------------------------------------------
extern "C" void kernel_launch(void* const* d_in, const int* in_sizes, int n_in,
                              void* d_out, int out_size) {
    const float* inputs = (const float*)d_in[0];   // [M_, D_]
    const float* protos = (const float*)d_in[1];   // [P_, D_]
    float* out = (float*)d_out;

    dim3 grid(P_ / BN, M_ / BM);   // (4, 128)
    dist_tf32_kernel<<<grid, 256>>>(inputs, protos, out);

    // Second tuple output: prototypes passed through unchanged.
    cudaMemcpyAsync(out + (size_t)M_ * P_, protos,
                    (size_t)P_ * D_ * sizeof(float),
                    cudaMemcpyDeviceToDevice);
}